// round 14
// baseline (speedup 1.0000x reference)
#include <cuda_runtime.h>
#include <cuda_fp16.h>
#include <cstdint>

// Problem constants
#define Bn 8
#define Hn 224
#define Wn 224
#define Cn 64
#define IN_DIM 576
#define RANKn 100
#define RPAD 128
#define FILTERS 256
#define HW 50176
#define PIX (Bn * HW)                 // 401408
#define XTOT (PIX * Cn)
#define NCONVBLK (XTOT / 16 / 256)    // 6272
#define NFOLD (RPAD + FILTERS)        // 384

// Stage-1 tiling (R7-proven): CTA 128 pixels x 128 rank, 4 warps 2x2, 64x64
#define CTA_M 128
#define BK 64
#define NT 128
#define KITERS (IN_DIM / BK)          // 9
#define STAGE_BYTES 32768
#define NSTAGE 3
#define SM_TOTAL (NSTAGE * STAGE_BYTES)   // 96KB -> 2 CTAs/SM

// Device-global scratch
__device__ __half g_Uh[RPAD * IN_DIM];     // U^T padded  [r][k]
__device__ __half g_M2h[FILTERS * RPAD];   // M^T padded  [n][r]
__device__ __half g_xh[XTOT];              // x fp16

// ---------------------------------------------------------------------------
__device__ __forceinline__ uint32_t smem_u32(const void* p) {
    uint32_t a;
    asm("{ .reg .u64 t; cvta.to.shared.u64 t, %1; cvt.u32.u64 %0, t; }"
        : "=r"(a) : "l"(p));
    return a;
}
#define CP_ASYNC_Z(d, s, sz) \
    asm volatile("cp.async.cg.shared.global [%0], [%1], 16, %2;" \
                 :: "r"(d), "l"(s), "r"(sz))
#define CP_ASYNC16(d, s) \
    asm volatile("cp.async.cg.shared.global [%0], [%1], 16;" :: "r"(d), "l"(s))
#define CP_COMMIT() asm volatile("cp.async.commit_group;" ::: "memory")
#define CP_WAIT(n)  asm volatile("cp.async.wait_group %0;" :: "n"(n) : "memory")

#define LDSM_X4(r0, r1, r2, r3, a) \
    asm volatile("ldmatrix.sync.aligned.m8n8.x4.shared.b16 {%0,%1,%2,%3}, [%4];" \
                 : "=r"(r0), "=r"(r1), "=r"(r2), "=r"(r3) : "r"(a))

#define MMA_F16(c, a, b0, b1)                                               \
    asm volatile("mma.sync.aligned.m16n8k16.row.col.f32.f16.f16.f32 "       \
                 "{%0,%1,%2,%3}, {%4,%5,%6,%7}, {%8,%9}, {%0,%1,%2,%3};"    \
                 : "+f"((c)[0]), "+f"((c)[1]), "+f"((c)[2]), "+f"((c)[3])   \
                 : "r"((a)[0]), "r"((a)[1]), "r"((a)[2]), "r"((a)[3]),      \
                   "r"(b0), "r"(b1))

// ---------------------------------------------------------------------------
// Fused prep: [0,RPAD) U^T rows; [RPAD,NFOLD) M^T rows; rest: x -> fp16.
// ---------------------------------------------------------------------------
__global__ void __launch_bounds__(256, 8)
prep_all(const float* __restrict__ x,
         const float* __restrict__ k_,
         const float* __restrict__ l_t,
         const float* __restrict__ s,
         const float* __restrict__ aux_U,
         const float* __restrict__ aux_Unp1,
         const float* __restrict__ aux_Vt,
         const float* __restrict__ aux_Vtnp1,
         const int* __restrict__ step_p) {
    const int tid = threadIdx.x;
    if (blockIdx.x >= NFOLD) {
        size_t idx = ((size_t)(blockIdx.x - NFOLD) * 256 + tid) * 16;
        const float4* xp = reinterpret_cast<const float4*>(x + idx);
        #pragma unroll
        for (int h = 0; h < 2; ++h) {
            float4 v0 = xp[h * 2 + 0];
            float4 v1 = xp[h * 2 + 1];
            __half2 hh[4];
            hh[0] = __float22half2_rn(make_float2(v0.x, v0.y));
            hh[1] = __float22half2_rn(make_float2(v0.z, v0.w));
            hh[2] = __float22half2_rn(make_float2(v1.x, v1.y));
            hh[3] = __float22half2_rn(make_float2(v1.z, v1.w));
            *reinterpret_cast<uint4*>(g_xh + idx + h * 8) =
                *reinterpret_cast<uint4*>(hh);
        }
        return;
    }
    const int st = *step_p;
    if (blockIdx.x < RPAD) {
        const int r = blockIdx.x;
        const float* U = (st == 0) ? k_ : (st == 1) ? aux_U : aux_Unp1;
        for (int k = tid; k < IN_DIM; k += 256) {
            float v = (r < RANKn) ? U[(size_t)k * RANKn + r] : 0.f;
            g_Uh[(size_t)r * IN_DIM + k] = __float2half_rn(v);
        }
        return;
    }
    __shared__ float VtCol[RANKn];
    __shared__ float Ms[RANKn];
    const int n = blockIdx.x - RPAD;
    if (st == 2) {
        if (tid < RANKn) VtCol[tid] = aux_Vtnp1[(size_t)tid * FILTERS + n];
        __syncthreads();
        if (tid < RANKn) {
            const float* sr = s + (size_t)tid * RANKn;
            float acc = 0.f;
            for (int q = 0; q < RANKn; ++q) acc += sr[q] * VtCol[q];
            Ms[tid] = acc;
        }
    } else {
        const float* V = (st == 0) ? aux_Vt : l_t;
        if (tid < RANKn) Ms[tid] = V[(size_t)tid * FILTERS + n];
    }
    __syncthreads();
    if (tid < RPAD)
        g_M2h[(size_t)n * RPAD + tid] =
            (tid < RANKn) ? __float2half_rn(Ms[tid]) : __float2half_rn(0.f);
}

// ---------------------------------------------------------------------------
// Fused main: stage 1 (patches @ U^T, R7 mainloop) keeps the 128x128 z1 tile
// on-chip, then stage 2 (z1 @ M^T) runs in two N-halves from smem.
// ---------------------------------------------------------------------------
__global__ void __launch_bounds__(NT, 2)
conv_fused(const float* __restrict__ bias_b,
           const float* __restrict__ bias_aux,
           const int* __restrict__ step_p,
           float* __restrict__ out) {
    extern __shared__ __align__(128) char smem[];
    const int tid  = threadIdx.x;
    const int lane = tid & 31;
    const int wid  = tid >> 5;
    const int mwarp = wid >> 1;
    const int nwarp = wid & 1;
    const int Mbase = blockIdx.x * CTA_M;
    const uint32_t sb = smem_u32(smem);

    const int jA  = tid & 7;
    const int rA  = tid >> 3;
    int hL[8], wL[8], bL[8];
    #pragma unroll
    for (int l = 0; l < 8; ++l) {
        int p = Mbase + l * 16 + rA;
        int bi = p / HW;
        int rem = p - bi * HW;
        hL[l] = rem / Wn;
        wL[l] = rem - hL[l] * Wn;
        bL[l] = bi;
    }

    float acc[4][8][4];
    #pragma unroll
    for (int mt = 0; mt < 4; ++mt)
        #pragma unroll
        for (int nt = 0; nt < 8; ++nt)
            #pragma unroll
            for (int q = 0; q < 4; ++q) acc[mt][nt][q] = 0.f;

    auto load_stage = [&](int ko) {
        const int stage = ko % NSTAGE;
        const int dh = ko / 3 - 1;
        const int dw = ko % 3 - 1;
        const uint32_t dA = sb + stage * STAGE_BYTES;
        #pragma unroll
        for (int l = 0; l < 8; ++l) {
            const int row = l * 16 + rA;
            const int hh = hL[l] + dh;
            const int ww = wL[l] + dw;
            const bool ok = ((unsigned)hh < (unsigned)Hn) &&
                            ((unsigned)ww < (unsigned)Wn);
            const __half* sp = ok
                ? g_xh + (((size_t)bL[l] * Hn + hh) * Wn + ww) * Cn + jA * 8
                : g_xh;
            CP_ASYNC_Z(dA + row * 128 + ((jA ^ (row & 7)) << 4), sp, ok ? 16u : 0u);
        }
        const int k0 = ko * BK;
        const uint32_t dB = dA + 16384;
        #pragma unroll
        for (int l = 0; l < 8; ++l) {
            const int n = l * 16 + rA;
            const __half* bs = g_Uh + (size_t)n * IN_DIM + k0 + jA * 8;
            CP_ASYNC16(dB + n * 128 + ((jA ^ (n & 7)) << 4), bs);
        }
    };

    const int m7  = lane & 7;
    const int khA = lane >> 4;
    const int khB = (lane >> 3) & 1;
    const uint32_t arow = (uint32_t)(mwarp * 64 + (lane & 15)) * 128;
    const uint32_t brow = (uint32_t)(nwarp * 64 + ((lane >> 4) << 3) + m7) * 128;
    uint32_t coffA[4], coffB[4];
    #pragma unroll
    for (int ks = 0; ks < 4; ++ks) {
        coffA[ks] = (uint32_t)(((ks * 2 + khA) ^ m7) << 4);
        coffB[ks] = (uint32_t)(((ks * 2 + khB) ^ m7) << 4);
    }

    load_stage(0); CP_COMMIT();
    load_stage(1); CP_COMMIT();

    for (int ko = 0; ko < KITERS; ++ko) {
        if (ko < KITERS - 1) CP_WAIT(1);
        else                 CP_WAIT(0);
        __syncthreads();
        if (ko + 2 < KITERS) { load_stage(ko + 2); CP_COMMIT(); }

        const uint32_t As = sb + (ko % NSTAGE) * STAGE_BYTES;
        const uint32_t Bs = As + 16384;
        #pragma unroll
        for (int ks = 0; ks < 4; ++ks) {
            uint32_t bf[4][4];
            #pragma unroll
            for (int np = 0; np < 4; ++np)
                LDSM_X4(bf[np][0], bf[np][1], bf[np][2], bf[np][3],
                        Bs + brow + np * (16 * 128) + coffB[ks]);
            uint32_t a[4][4];
            #pragma unroll
            for (int mt = 0; mt < 4; ++mt)
                LDSM_X4(a[mt][0], a[mt][1], a[mt][2], a[mt][3],
                        As + arow + mt * (16 * 128) + coffA[ks]);
            #pragma unroll
            for (int mt = 0; mt < 4; ++mt)
                #pragma unroll
                for (int nt = 0; nt < 8; ++nt)
                    MMA_F16(acc[mt][nt], a[mt],
                            bf[nt >> 1][(nt & 1) * 2],
                            bf[nt >> 1][(nt & 1) * 2 + 1]);
        }
    }

    // ---- stage 1 -> 2 handoff -------------------------------------------
    __syncthreads();   // all warps done with all stage buffers

    // Prefetch BOTH M2 halves: rows 0..255, 256B/row -> smem [32768, 98304)
    #pragma unroll
    for (int l = 0; l < 32; ++l) {
        int idx = l * NT + tid;
        int row = idx >> 4, j = idx & 15;
        const __half* bsrc = g_M2h + (size_t)row * RPAD + j * 8;
        CP_ASYNC16(sb + 32768 + row * 256 + ((j ^ (row & 7)) << 4), bsrc);
    }
    CP_COMMIT();

    // Store z1 tile (fp16) into smem [0, 32768): row = local pixel, 256B rows
    const int g  = lane >> 2;
    const int tq = lane & 3;
    #pragma unroll
    for (int mt = 0; mt < 4; ++mt) {
        #pragma unroll
        for (int half = 0; half < 2; ++half) {
            const int rl = mwarp * 64 + mt * 16 + g + half * 8;
            #pragma unroll
            for (int nt = 0; nt < 8; ++nt) {
                const int j = nwarp * 8 + nt;        // 16B chunk index
                __half2 v = __floats2half2_rn(acc[mt][nt][half * 2 + 0],
                                              acc[mt][nt][half * 2 + 1]);
                *reinterpret_cast<__half2*>(
                    smem + rl * 256 + ((j ^ (rl & 7)) << 4) + tq * 4) = v;
            }
        }
    }
    CP_WAIT(0);
    __syncthreads();

    // ---- stage 2: two N-halves of out = relu(z1 @ M^T + bias) ----------
    const float* bias = (*step_p == 2) ? bias_b : bias_aux;
    const uint32_t arow2 = (uint32_t)(mwarp * 64 + (lane & 15)) * 256;
    const uint32_t brow2 = (uint32_t)(nwarp * 64 + ((lane >> 4) << 3) + m7) * 256;

    #pragma unroll
    for (int npass = 0; npass < 2; ++npass) {
        #pragma unroll
        for (int mt = 0; mt < 4; ++mt)
            #pragma unroll
            for (int nt = 0; nt < 8; ++nt)
                #pragma unroll
                for (int q = 0; q < 4; ++q) acc[mt][nt][q] = 0.f;

        const uint32_t Bb = sb + 32768 + npass * 32768;
        #pragma unroll
        for (int ks = 0; ks < 8; ++ks) {
            const uint32_t cA = (uint32_t)(((ks * 2 + khA) ^ m7) << 4);
            const uint32_t cB = (uint32_t)(((ks * 2 + khB) ^ m7) << 4);
            uint32_t bf[4][4];
            #pragma unroll
            for (int np = 0; np < 4; ++np)
                LDSM_X4(bf[np][0], bf[np][1], bf[np][2], bf[np][3],
                        Bb + brow2 + np * (16 * 256) + cB);
            uint32_t a[4][4];
            #pragma unroll
            for (int mt = 0; mt < 4; ++mt)
                LDSM_X4(a[mt][0], a[mt][1], a[mt][2], a[mt][3],
                        sb + arow2 + mt * (16 * 256) + cA);
            #pragma unroll
            for (int mt = 0; mt < 4; ++mt)
                #pragma unroll
                for (int nt = 0; nt < 8; ++nt)
                    MMA_F16(acc[mt][nt], a[mt],
                            bf[nt >> 1][(nt & 1) * 2],
                            bf[nt >> 1][(nt & 1) * 2 + 1]);
        }

        const int Nbase = npass * 128;
        #pragma unroll
        for (int mt = 0; mt < 4; ++mt) {
            const int r0 = Mbase + mwarp * 64 + mt * 16 + g;
            #pragma unroll
            for (int half = 0; half < 2; ++half) {
                const int r = r0 + half * 8;
                const int bi = r / HW;
                const int rr = r - bi * HW;
                const float* bp = bias + (size_t)rr * FILTERS;
                float* op = out + (size_t)r * FILTERS;
                #pragma unroll
                for (int nt = 0; nt < 8; ++nt) {
                    const int col = Nbase + nwarp * 64 + nt * 8 + tq * 2;
                    const float2 bv = *reinterpret_cast<const float2*>(bp + col);
                    float2 o;
                    o.x = fmaxf(acc[mt][nt][half * 2 + 0] + bv.x, 0.f);
                    o.y = fmaxf(acc[mt][nt][half * 2 + 1] + bv.y, 0.f);
                    *reinterpret_cast<float2*>(op + col) = o;
                }
            }
        }
    }
}

// ---------------------------------------------------------------------------
// Inputs: 0:x 1:k 2:l_t 3:s 4:aux_U 5:aux_Unp1 6:aux_Vt 7:aux_Vtnp1
//         8:b 9:aux_b 10:step
// ---------------------------------------------------------------------------
extern "C" void kernel_launch(void* const* d_in, const int* in_sizes, int n_in,
                              void* d_out, int out_size) {
    const float* x         = (const float*)d_in[0];
    const float* k_        = (const float*)d_in[1];
    const float* l_t       = (const float*)d_in[2];
    const float* s         = (const float*)d_in[3];
    const float* aux_U     = (const float*)d_in[4];
    const float* aux_Unp1  = (const float*)d_in[5];
    const float* aux_Vt    = (const float*)d_in[6];
    const float* aux_Vtnp1 = (const float*)d_in[7];
    const float* bias_b    = (const float*)d_in[8];
    const float* bias_aux  = (const float*)d_in[9];
    const int*   step_p    = (const int*)d_in[10];
    float* out = (float*)d_out;

    static bool cfg_done = false;
    if (!cfg_done) {
        cudaFuncSetAttribute(conv_fused,
                             cudaFuncAttributeMaxDynamicSharedMemorySize, SM_TOTAL);
        cfg_done = true;
    }

    prep_all<<<NFOLD + NCONVBLK, 256>>>(x, k_, l_t, s, aux_U, aux_Unp1,
                                        aux_Vt, aux_Vtnp1, step_p);
    conv_fused<<<PIX / CTA_M, NT, SM_TOTAL>>>(bias_b, bias_aux, step_p, out);
}

// round 15
// speedup vs baseline: 1.0055x; 1.0055x over previous
#include <cuda_runtime.h>
#include <cuda_fp16.h>
#include <cstdint>

// Problem constants
#define Bn 8
#define Hn 224
#define Wn 224
#define Cn 64
#define IN_DIM 576
#define RANKn 100
#define RPAD 128
#define FILTERS 256
#define HW 50176
#define PIX (Bn * HW)                 // 401408
#define XTOT (PIX * Cn)
#define NCONVBLK (XTOT / 16 / 256)    // 6272
#define NFOLD (RPAD + FILTERS)        // 384

// Stage-1 tiling (R7-proven): CTA 128 pixels x 128 rank, 4 warps 2x2, 64x64
#define CTA_M 128
#define BK 64
#define NT 128
#define KITERS (IN_DIM / BK)          // 9
#define STAGE_BYTES 32768
#define NSTAGE 3
#define SM1_TOTAL (NSTAGE * STAGE_BYTES)   // 96KB
// Stage-2: A once (32KB) + full M2 (64KB) = 96KB -> 2 CTAs/SM
#define SM2_TOTAL 98304

// Device-global scratch
__device__ __half g_Uh[RPAD * IN_DIM];      // U^T padded  [r][k]
__device__ __half g_M2h[FILTERS * RPAD];    // M^T padded  [n][r]
__device__ __half g_xh[XTOT];               // x fp16
__device__ __half g_z1[(size_t)PIX * RPAD]; // intermediate

// ---------------------------------------------------------------------------
__device__ __forceinline__ uint32_t smem_u32(const void* p) {
    uint32_t a;
    asm("{ .reg .u64 t; cvta.to.shared.u64 t, %1; cvt.u32.u64 %0, t; }"
        : "=r"(a) : "l"(p));
    return a;
}
#define CP_ASYNC_Z(d, s, sz) \
    asm volatile("cp.async.cg.shared.global [%0], [%1], 16, %2;" \
                 :: "r"(d), "l"(s), "r"(sz))
#define CP_ASYNC16(d, s) \
    asm volatile("cp.async.cg.shared.global [%0], [%1], 16;" :: "r"(d), "l"(s))
#define CP_COMMIT() asm volatile("cp.async.commit_group;" ::: "memory")
#define CP_WAIT(n)  asm volatile("cp.async.wait_group %0;" :: "n"(n) : "memory")

#define LDSM_X4(r0, r1, r2, r3, a) \
    asm volatile("ldmatrix.sync.aligned.m8n8.x4.shared.b16 {%0,%1,%2,%3}, [%4];" \
                 : "=r"(r0), "=r"(r1), "=r"(r2), "=r"(r3) : "r"(a))

#define MMA_F16(c, a, b0, b1)                                               \
    asm volatile("mma.sync.aligned.m16n8k16.row.col.f32.f16.f16.f32 "       \
                 "{%0,%1,%2,%3}, {%4,%5,%6,%7}, {%8,%9}, {%0,%1,%2,%3};"    \
                 : "+f"((c)[0]), "+f"((c)[1]), "+f"((c)[2]), "+f"((c)[3])   \
                 : "r"((a)[0]), "r"((a)[1]), "r"((a)[2]), "r"((a)[3]),      \
                   "r"(b0), "r"(b1))

// ---------------------------------------------------------------------------
// Fused prep: [0,RPAD) U^T rows; [RPAD,NFOLD) M^T rows; rest: x -> fp16.
// ---------------------------------------------------------------------------
__global__ void __launch_bounds__(256, 8)
prep_all(const float* __restrict__ x,
         const float* __restrict__ k_,
         const float* __restrict__ l_t,
         const float* __restrict__ s,
         const float* __restrict__ aux_U,
         const float* __restrict__ aux_Unp1,
         const float* __restrict__ aux_Vt,
         const float* __restrict__ aux_Vtnp1,
         const int* __restrict__ step_p) {
    const int tid = threadIdx.x;
    if (blockIdx.x >= NFOLD) {
        size_t idx = ((size_t)(blockIdx.x - NFOLD) * 256 + tid) * 16;
        const float4* xp = reinterpret_cast<const float4*>(x + idx);
        #pragma unroll
        for (int h = 0; h < 2; ++h) {
            float4 v0 = xp[h * 2 + 0];
            float4 v1 = xp[h * 2 + 1];
            __half2 hh[4];
            hh[0] = __float22half2_rn(make_float2(v0.x, v0.y));
            hh[1] = __float22half2_rn(make_float2(v0.z, v0.w));
            hh[2] = __float22half2_rn(make_float2(v1.x, v1.y));
            hh[3] = __float22half2_rn(make_float2(v1.z, v1.w));
            *reinterpret_cast<uint4*>(g_xh + idx + h * 8) =
                *reinterpret_cast<uint4*>(hh);
        }
        return;
    }
    const int st = *step_p;
    if (blockIdx.x < RPAD) {
        const int r = blockIdx.x;
        const float* U = (st == 0) ? k_ : (st == 1) ? aux_U : aux_Unp1;
        for (int k = tid; k < IN_DIM; k += 256) {
            float v = (r < RANKn) ? U[(size_t)k * RANKn + r] : 0.f;
            g_Uh[(size_t)r * IN_DIM + k] = __float2half_rn(v);
        }
        return;
    }
    __shared__ float VtCol[RANKn];
    __shared__ float Ms[RANKn];
    const int n = blockIdx.x - RPAD;
    if (st == 2) {
        if (tid < RANKn) VtCol[tid] = aux_Vtnp1[(size_t)tid * FILTERS + n];
        __syncthreads();
        if (tid < RANKn) {
            const float* sr = s + (size_t)tid * RANKn;
            float acc = 0.f;
            for (int q = 0; q < RANKn; ++q) acc += sr[q] * VtCol[q];
            Ms[tid] = acc;
        }
    } else {
        const float* V = (st == 0) ? aux_Vt : l_t;
        if (tid < RANKn) Ms[tid] = V[(size_t)tid * FILTERS + n];
    }
    __syncthreads();
    if (tid < RPAD)
        g_M2h[(size_t)n * RPAD + tid] =
            (tid < RANKn) ? __float2half_rn(Ms[tid]) : __float2half_rn(0.f);
}

// ---------------------------------------------------------------------------
// Stage 1: z1[pix][128] = patches @ U^T   (R7 conv body, N fixed = 128)
// ---------------------------------------------------------------------------
__global__ void __launch_bounds__(NT, 2)
z1k() {
    extern __shared__ __align__(128) char smem[];
    const int tid  = threadIdx.x;
    const int lane = tid & 31;
    const int wid  = tid >> 5;
    const int mwarp = wid >> 1;
    const int nwarp = wid & 1;
    const int Mbase = blockIdx.x * CTA_M;
    const uint32_t sb = smem_u32(smem);

    const int jA  = tid & 7;
    const int rA  = tid >> 3;
    int hL[8], wL[8], bL[8];
    #pragma unroll
    for (int l = 0; l < 8; ++l) {
        int p = Mbase + l * 16 + rA;
        int bi = p / HW;
        int rem = p - bi * HW;
        hL[l] = rem / Wn;
        wL[l] = rem - hL[l] * Wn;
        bL[l] = bi;
    }

    float acc[4][8][4];
    #pragma unroll
    for (int mt = 0; mt < 4; ++mt)
        #pragma unroll
        for (int nt = 0; nt < 8; ++nt)
            #pragma unroll
            for (int q = 0; q < 4; ++q) acc[mt][nt][q] = 0.f;

    auto load_stage = [&](int ko) {
        const int stage = ko % NSTAGE;
        const int dh = ko / 3 - 1;
        const int dw = ko % 3 - 1;
        const uint32_t dA = sb + stage * STAGE_BYTES;
        #pragma unroll
        for (int l = 0; l < 8; ++l) {
            const int row = l * 16 + rA;
            const int hh = hL[l] + dh;
            const int ww = wL[l] + dw;
            const bool ok = ((unsigned)hh < (unsigned)Hn) &&
                            ((unsigned)ww < (unsigned)Wn);
            const __half* sp = ok
                ? g_xh + (((size_t)bL[l] * Hn + hh) * Wn + ww) * Cn + jA * 8
                : g_xh;
            CP_ASYNC_Z(dA + row * 128 + ((jA ^ (row & 7)) << 4), sp, ok ? 16u : 0u);
        }
        const int k0 = ko * BK;
        const uint32_t dB = dA + 16384;
        #pragma unroll
        for (int l = 0; l < 8; ++l) {
            const int n = l * 16 + rA;
            const __half* bs = g_Uh + (size_t)n * IN_DIM + k0 + jA * 8;
            CP_ASYNC16(dB + n * 128 + ((jA ^ (n & 7)) << 4), bs);
        }
    };

    const int m7  = lane & 7;
    const int khA = lane >> 4;
    const int khB = (lane >> 3) & 1;
    const uint32_t arow = (uint32_t)(mwarp * 64 + (lane & 15)) * 128;
    const uint32_t brow = (uint32_t)(nwarp * 64 + ((lane >> 4) << 3) + m7) * 128;
    uint32_t coffA[4], coffB[4];
    #pragma unroll
    for (int ks = 0; ks < 4; ++ks) {
        coffA[ks] = (uint32_t)(((ks * 2 + khA) ^ m7) << 4);
        coffB[ks] = (uint32_t)(((ks * 2 + khB) ^ m7) << 4);
    }

    load_stage(0); CP_COMMIT();
    load_stage(1); CP_COMMIT();

    for (int ko = 0; ko < KITERS; ++ko) {
        if (ko < KITERS - 1) CP_WAIT(1);
        else                 CP_WAIT(0);
        __syncthreads();
        if (ko + 2 < KITERS) { load_stage(ko + 2); CP_COMMIT(); }

        const uint32_t As = sb + (ko % NSTAGE) * STAGE_BYTES;
        const uint32_t Bs = As + 16384;
        #pragma unroll
        for (int ks = 0; ks < 4; ++ks) {
            uint32_t bf[4][4];
            #pragma unroll
            for (int np = 0; np < 4; ++np)
                LDSM_X4(bf[np][0], bf[np][1], bf[np][2], bf[np][3],
                        Bs + brow + np * (16 * 128) + coffB[ks]);
            uint32_t a[4][4];
            #pragma unroll
            for (int mt = 0; mt < 4; ++mt)
                LDSM_X4(a[mt][0], a[mt][1], a[mt][2], a[mt][3],
                        As + arow + mt * (16 * 128) + coffA[ks]);
            #pragma unroll
            for (int mt = 0; mt < 4; ++mt)
                #pragma unroll
                for (int nt = 0; nt < 8; ++nt)
                    MMA_F16(acc[mt][nt], a[mt],
                            bf[nt >> 1][(nt & 1) * 2],
                            bf[nt >> 1][(nt & 1) * 2 + 1]);
        }
    }

    // Epilogue: fp16 z1 store
    const int g  = lane >> 2;
    const int tq = lane & 3;
    #pragma unroll
    for (int mt = 0; mt < 4; ++mt) {
        #pragma unroll
        for (int half = 0; half < 2; ++half) {
            const int r = Mbase + mwarp * 64 + mt * 16 + g + half * 8;
            __half* zp = g_z1 + (size_t)r * RPAD;
            #pragma unroll
            for (int nt = 0; nt < 8; ++nt) {
                const int col = nwarp * 64 + nt * 8 + tq * 2;
                __half2 v = __floats2half2_rn(acc[mt][nt][half * 2 + 0],
                                              acc[mt][nt][half * 2 + 1]);
                *reinterpret_cast<__half2*>(zp + col) = v;
            }
        }
    }
}

// ---------------------------------------------------------------------------
// Stage 2: out = relu(z1 @ M^T + bias). CTA = 128 pix x 256 filters.
// A tile loaded ONCE (32KB); full M2 (64KB) resident; two 128-wide N passes.
// ---------------------------------------------------------------------------
__global__ void __launch_bounds__(NT, 2)
gemm2(const float* __restrict__ bias_b,
      const float* __restrict__ bias_aux,
      const int* __restrict__ step_p,
      float* __restrict__ out) {
    extern __shared__ __align__(128) char smem[];
    const int tid  = threadIdx.x;
    const int lane = tid & 31;
    const int wid  = tid >> 5;
    const int mwarp = wid >> 1;
    const int nwarp = wid & 1;
    const int Mbase = blockIdx.x * CTA_M;
    const uint32_t sb  = smem_u32(smem);
    const uint32_t sbB = sb + 32768;

    // Load A tile once: 128 rows x 256B
    #pragma unroll
    for (int l = 0; l < 16; ++l) {
        int idx = l * NT + tid;
        int row = idx >> 4, j = idx & 15;
        const __half* asrc = g_z1 + (size_t)(Mbase + row) * RPAD + j * 8;
        CP_ASYNC16(sb + row * 256 + ((j ^ (row & 7)) << 4), asrc);
    }
    // Load full M2: 256 rows x 256B
    #pragma unroll
    for (int l = 0; l < 32; ++l) {
        int idx = l * NT + tid;
        int row = idx >> 4, j = idx & 15;
        const __half* bsrc = g_M2h + (size_t)row * RPAD + j * 8;
        CP_ASYNC16(sbB + row * 256 + ((j ^ (row & 7)) << 4), bsrc);
    }
    CP_COMMIT();

    const int m7  = lane & 7;
    const int khA = lane >> 4;
    const int khB = (lane >> 3) & 1;
    const uint32_t arow = (uint32_t)(mwarp * 64 + (lane & 15)) * 256;
    const uint32_t brow = (uint32_t)(nwarp * 64 + ((lane >> 4) << 3) + m7) * 256;

    const float* bias = (*step_p == 2) ? bias_b : bias_aux;
    const int g  = lane >> 2;
    const int tq = lane & 3;

    CP_WAIT(0);
    __syncthreads();

    #pragma unroll
    for (int npass = 0; npass < 2; ++npass) {
        float acc[4][8][4];
        #pragma unroll
        for (int mt = 0; mt < 4; ++mt)
            #pragma unroll
            for (int nt = 0; nt < 8; ++nt)
                #pragma unroll
                for (int q = 0; q < 4; ++q) acc[mt][nt][q] = 0.f;

        const uint32_t Bb = sbB + npass * 32768;   // 128 filters per pass
        #pragma unroll
        for (int ks = 0; ks < 8; ++ks) {
            const uint32_t cA = (uint32_t)(((ks * 2 + khA) ^ m7) << 4);
            const uint32_t cB = (uint32_t)(((ks * 2 + khB) ^ m7) << 4);
            uint32_t bf[4][4];
            #pragma unroll
            for (int np = 0; np < 4; ++np)
                LDSM_X4(bf[np][0], bf[np][1], bf[np][2], bf[np][3],
                        Bb + brow + np * (16 * 256) + cB);
            uint32_t a[4][4];
            #pragma unroll
            for (int mt = 0; mt < 4; ++mt)
                LDSM_X4(a[mt][0], a[mt][1], a[mt][2], a[mt][3],
                        sb + arow + mt * (16 * 256) + cA);
            #pragma unroll
            for (int mt = 0; mt < 4; ++mt)
                #pragma unroll
                for (int nt = 0; nt < 8; ++nt)
                    MMA_F16(acc[mt][nt], a[mt],
                            bf[nt >> 1][(nt & 1) * 2],
                            bf[nt >> 1][(nt & 1) * 2 + 1]);
        }

        const int Nbase = npass * 128;
        #pragma unroll
        for (int mt = 0; mt < 4; ++mt) {
            const int r0 = Mbase + mwarp * 64 + mt * 16 + g;
            #pragma unroll
            for (int half = 0; half < 2; ++half) {
                const int r = r0 + half * 8;
                const int bi = r / HW;
                const int rr = r - bi * HW;
                const float* bp = bias + (size_t)rr * FILTERS;
                float* op = out + (size_t)r * FILTERS;
                #pragma unroll
                for (int nt = 0; nt < 8; ++nt) {
                    const int col = Nbase + nwarp * 64 + nt * 8 + tq * 2;
                    const float2 bv = *reinterpret_cast<const float2*>(bp + col);
                    float2 o;
                    o.x = fmaxf(acc[mt][nt][half * 2 + 0] + bv.x, 0.f);
                    o.y = fmaxf(acc[mt][nt][half * 2 + 1] + bv.y, 0.f);
                    *reinterpret_cast<float2*>(op + col) = o;
                }
            }
        }
    }
}

// ---------------------------------------------------------------------------
// Inputs: 0:x 1:k 2:l_t 3:s 4:aux_U 5:aux_Unp1 6:aux_Vt 7:aux_Vtnp1
//         8:b 9:aux_b 10:step
// ---------------------------------------------------------------------------
extern "C" void kernel_launch(void* const* d_in, const int* in_sizes, int n_in,
                              void* d_out, int out_size) {
    const float* x         = (const float*)d_in[0];
    const float* k_        = (const float*)d_in[1];
    const float* l_t       = (const float*)d_in[2];
    const float* s         = (const float*)d_in[3];
    const float* aux_U     = (const float*)d_in[4];
    const float* aux_Unp1  = (const float*)d_in[5];
    const float* aux_Vt    = (const float*)d_in[6];
    const float* aux_Vtnp1 = (const float*)d_in[7];
    const float* bias_b    = (const float*)d_in[8];
    const float* bias_aux  = (const float*)d_in[9];
    const int*   step_p    = (const int*)d_in[10];
    float* out = (float*)d_out;

    static bool cfg_done = false;
    if (!cfg_done) {
        cudaFuncSetAttribute(z1k,
                             cudaFuncAttributeMaxDynamicSharedMemorySize, SM1_TOTAL);
        cudaFuncSetAttribute(gemm2,
                             cudaFuncAttributeMaxDynamicSharedMemorySize, SM2_TOTAL);
        cfg_done = true;
    }

    prep_all<<<NFOLD + NCONVBLK, 256>>>(x, k_, l_t, s, aux_U, aux_Unp1,
                                        aux_Vt, aux_Vtnp1, step_p);
    z1k<<<PIX / CTA_M, NT, SM1_TOTAL>>>();
    gemm2<<<PIX / CTA_M, NT, SM2_TOTAL>>>(bias_b, bias_aux, step_p, out);
}

// round 16
// speedup vs baseline: 1.0916x; 1.0857x over previous
#include <cuda_runtime.h>
#include <cuda_fp16.h>
#include <cstdint>

// Problem constants
#define Bn 8
#define Hn 224
#define Wn 224
#define Cn 64
#define IN_DIM 576
#define RANKn 100
#define RPAD 128
#define FILTERS 256
#define HW 50176
#define PIX (Bn * HW)                 // 401408
#define XTOT (PIX * Cn)
#define NCONVBLK (XTOT / 16 / 256)    // 6272
#define NFOLD (RPAD + FILTERS)        // 384

// Fused tiling: CTA 128 pixels x 128 rank; 4 warps stacked in M (32 rows each),
// every warp owns the FULL rank dimension (stage-1 acc == stage-2 A operand).
#define CTA_M 128
#define BK 64
#define NT 128
#define KITERS (IN_DIM / BK)          // 9
#define STAGE_BYTES 32768             // A 16KB + B 16KB
#define NSTAGE 3
#define SM_TOTAL (NSTAGE * STAGE_BYTES)   // 96KB -> 2 CTAs/SM

// Device-global scratch
__device__ __half g_Uh[RPAD * IN_DIM];      // U^T padded  [r][k]
__device__ __half g_M2h[FILTERS * RPAD];    // M^T padded  [n][r]
__device__ __half g_xh[XTOT];               // x fp16

// ---------------------------------------------------------------------------
__device__ __forceinline__ uint32_t smem_u32(const void* p) {
    uint32_t a;
    asm("{ .reg .u64 t; cvta.to.shared.u64 t, %1; cvt.u32.u64 %0, t; }"
        : "=r"(a) : "l"(p));
    return a;
}
#define CP_ASYNC_Z(d, s, sz) \
    asm volatile("cp.async.cg.shared.global [%0], [%1], 16, %2;" \
                 :: "r"(d), "l"(s), "r"(sz))
#define CP_ASYNC16(d, s) \
    asm volatile("cp.async.cg.shared.global [%0], [%1], 16;" :: "r"(d), "l"(s))
#define CP_COMMIT() asm volatile("cp.async.commit_group;" ::: "memory")
#define CP_WAIT(n)  asm volatile("cp.async.wait_group %0;" :: "n"(n) : "memory")

#define LDSM_X4(r0, r1, r2, r3, a) \
    asm volatile("ldmatrix.sync.aligned.m8n8.x4.shared.b16 {%0,%1,%2,%3}, [%4];" \
                 : "=r"(r0), "=r"(r1), "=r"(r2), "=r"(r3) : "r"(a))

#define MMA_F16(c, a0, a1, a2, a3, b0, b1)                                  \
    asm volatile("mma.sync.aligned.m16n8k16.row.col.f32.f16.f16.f32 "       \
                 "{%0,%1,%2,%3}, {%4,%5,%6,%7}, {%8,%9}, {%0,%1,%2,%3};"    \
                 : "+f"((c)[0]), "+f"((c)[1]), "+f"((c)[2]), "+f"((c)[3])   \
                 : "r"(a0), "r"(a1), "r"(a2), "r"(a3), "r"(b0), "r"(b1))

// ---------------------------------------------------------------------------
// Fused prep: [0,RPAD) U^T rows; [RPAD,NFOLD) M^T rows; rest: x -> fp16.
// ---------------------------------------------------------------------------
__global__ void __launch_bounds__(256, 8)
prep_all(const float* __restrict__ x,
         const float* __restrict__ k_,
         const float* __restrict__ l_t,
         const float* __restrict__ s,
         const float* __restrict__ aux_U,
         const float* __restrict__ aux_Unp1,
         const float* __restrict__ aux_Vt,
         const float* __restrict__ aux_Vtnp1,
         const int* __restrict__ step_p) {
    const int tid = threadIdx.x;
    if (blockIdx.x >= NFOLD) {
        size_t idx = ((size_t)(blockIdx.x - NFOLD) * 256 + tid) * 16;
        const float4* xp = reinterpret_cast<const float4*>(x + idx);
        #pragma unroll
        for (int h = 0; h < 2; ++h) {
            float4 v0 = xp[h * 2 + 0];
            float4 v1 = xp[h * 2 + 1];
            __half2 hh[4];
            hh[0] = __float22half2_rn(make_float2(v0.x, v0.y));
            hh[1] = __float22half2_rn(make_float2(v0.z, v0.w));
            hh[2] = __float22half2_rn(make_float2(v1.x, v1.y));
            hh[3] = __float22half2_rn(make_float2(v1.z, v1.w));
            *reinterpret_cast<uint4*>(g_xh + idx + h * 8) =
                *reinterpret_cast<uint4*>(hh);
        }
        return;
    }
    const int st = *step_p;
    if (blockIdx.x < RPAD) {
        const int r = blockIdx.x;
        const float* U = (st == 0) ? k_ : (st == 1) ? aux_U : aux_Unp1;
        for (int k = tid; k < IN_DIM; k += 256) {
            float v = (r < RANKn) ? U[(size_t)k * RANKn + r] : 0.f;
            g_Uh[(size_t)r * IN_DIM + k] = __float2half_rn(v);
        }
        return;
    }
    __shared__ float VtCol[RANKn];
    __shared__ float Ms[RANKn];
    const int n = blockIdx.x - RPAD;
    if (st == 2) {
        if (tid < RANKn) VtCol[tid] = aux_Vtnp1[(size_t)tid * FILTERS + n];
        __syncthreads();
        if (tid < RANKn) {
            const float* sr = s + (size_t)tid * RANKn;
            float acc = 0.f;
            for (int q = 0; q < RANKn; ++q) acc += sr[q] * VtCol[q];
            Ms[tid] = acc;
        }
    } else {
        const float* V = (st == 0) ? aux_Vt : l_t;
        if (tid < RANKn) Ms[tid] = V[(size_t)tid * FILTERS + n];
    }
    __syncthreads();
    if (tid < RPAD)
        g_M2h[(size_t)n * RPAD + tid] =
            (tid < RANKn) ? __float2half_rn(Ms[tid]) : __float2half_rn(0.f);
}

// ---------------------------------------------------------------------------
// Fused main: stage 1 (patches @ U^T) -> acc regs -> pack to fp16 A fragments
// -> stage 2 (z1 @ M^T) straight from registers. z1 never touches memory.
// ---------------------------------------------------------------------------
__global__ void __launch_bounds__(NT, 2)
conv_fused(const float* __restrict__ bias_b,
           const float* __restrict__ bias_aux,
           const int* __restrict__ step_p,
           float* __restrict__ out) {
    extern __shared__ __align__(128) char smem[];
    const int tid  = threadIdx.x;
    const int lane = tid & 31;
    const int mwarp = tid >> 5;           // 0..3, M-stacked warps
    const int Mbase = blockIdx.x * CTA_M;
    const uint32_t sb = smem_u32(smem);

    // Loader geometry (packed coords, 8 regs)
    const int jA  = tid & 7;
    const int rA  = tid >> 3;
    uint32_t pc[8];
    #pragma unroll
    for (int l = 0; l < 8; ++l) {
        int p = Mbase + l * 16 + rA;
        int bi = p / HW;
        int rem = p - bi * HW;
        int h = rem / Wn;
        int w = rem - h * Wn;
        pc[l] = ((uint32_t)bi << 16) | ((uint32_t)h << 8) | (uint32_t)w;
    }

    float acc[2][16][4];                   // 32 M x 128 N(rank) per warp
    #pragma unroll
    for (int mt = 0; mt < 2; ++mt)
        #pragma unroll
        for (int nt = 0; nt < 16; ++nt)
            #pragma unroll
            for (int q = 0; q < 4; ++q) acc[mt][nt][q] = 0.f;

    auto load_stage = [&](int ko) {
        const int stage = ko % NSTAGE;
        const int dh = ko / 3 - 1;
        const int dw = ko % 3 - 1;
        const uint32_t dA = sb + stage * STAGE_BYTES;
        #pragma unroll
        for (int l = 0; l < 8; ++l) {
            const int row = l * 16 + rA;
            const int hh = (int)((pc[l] >> 8) & 255u) + dh;
            const int ww = (int)(pc[l] & 255u) + dw;
            const int bi = (int)(pc[l] >> 16);
            const bool ok = ((unsigned)hh < (unsigned)Hn) &&
                            ((unsigned)ww < (unsigned)Wn);
            const __half* sp = ok
                ? g_xh + (((size_t)bi * Hn + hh) * Wn + ww) * Cn + jA * 8
                : g_xh;
            CP_ASYNC_Z(dA + row * 128 + ((jA ^ (row & 7)) << 4), sp, ok ? 16u : 0u);
        }
        const int k0 = ko * BK;
        const uint32_t dB = dA + 16384;
        #pragma unroll
        for (int l = 0; l < 8; ++l) {
            const int n = l * 16 + rA;
            const __half* bs = g_Uh + (size_t)n * IN_DIM + k0 + jA * 8;
            CP_ASYNC16(dB + n * 128 + ((jA ^ (n & 7)) << 4), bs);
        }
    };

    // Fragment addressing
    const int m7  = lane & 7;
    const int khA = lane >> 4;
    const int khB = (lane >> 3) & 1;
    const uint32_t arow = (uint32_t)(mwarp * 32 + (lane & 15)) * 128;
    const uint32_t brow = (uint32_t)(((lane >> 4) << 3) + m7) * 128;
    uint32_t coffA[4], coffB[4];
    #pragma unroll
    for (int ks = 0; ks < 4; ++ks) {
        coffA[ks] = (uint32_t)(((ks * 2 + khA) ^ m7) << 4);
        coffB[ks] = (uint32_t)(((ks * 2 + khB) ^ m7) << 4);
    }

    load_stage(0); CP_COMMIT();
    load_stage(1); CP_COMMIT();

    for (int ko = 0; ko < KITERS; ++ko) {
        if (ko < KITERS - 1) CP_WAIT(1);
        else                 CP_WAIT(0);
        __syncthreads();
        if (ko + 2 < KITERS) { load_stage(ko + 2); CP_COMMIT(); }

        const uint32_t As = sb + (ko % NSTAGE) * STAGE_BYTES;
        const uint32_t Bs = As + 16384;
        #pragma unroll
        for (int ks = 0; ks < 4; ++ks) {
            uint32_t bf[8][4];
            #pragma unroll
            for (int np = 0; np < 8; ++np)
                LDSM_X4(bf[np][0], bf[np][1], bf[np][2], bf[np][3],
                        Bs + brow + np * (16 * 128) + coffB[ks]);
            uint32_t a[2][4];
            #pragma unroll
            for (int mt = 0; mt < 2; ++mt)
                LDSM_X4(a[mt][0], a[mt][1], a[mt][2], a[mt][3],
                        As + arow + mt * (16 * 128) + coffA[ks]);
            #pragma unroll
            for (int mt = 0; mt < 2; ++mt)
                #pragma unroll
                for (int nt = 0; nt < 16; ++nt)
                    MMA_F16(acc[mt][nt], a[mt][0], a[mt][1], a[mt][2], a[mt][3],
                            bf[nt >> 1][(nt & 1) * 2],
                            bf[nt >> 1][(nt & 1) * 2 + 1]);
        }
    }

    // ---- register handoff: pack acc (C-layout) into stage-2 A fragments ----
    __syncthreads();   // all stage buffers dead

    // Prefetch full M2 (256 rows x 256B = 64KB) into recycled stage smem
    #pragma unroll
    for (int l = 0; l < 32; ++l) {
        int idx = l * NT + tid;
        int row = idx >> 4, j = idx & 15;
        const __half* bsrc = g_M2h + (size_t)row * RPAD + j * 8;
        CP_ASYNC16(sb + row * 256 + ((j ^ (row & 7)) << 4), bsrc);
    }
    CP_COMMIT();

    // Pack: A m16k16 fragment j <- C n-tiles (2j, 2j+1)
    uint32_t a2[2][8][4];
    #pragma unroll
    for (int mt = 0; mt < 2; ++mt)
        #pragma unroll
        for (int j = 0; j < 8; ++j) {
            __half2 h0 = __floats2half2_rn(acc[mt][2*j][0],   acc[mt][2*j][1]);
            __half2 h1 = __floats2half2_rn(acc[mt][2*j][2],   acc[mt][2*j][3]);
            __half2 h2 = __floats2half2_rn(acc[mt][2*j+1][0], acc[mt][2*j+1][1]);
            __half2 h3 = __floats2half2_rn(acc[mt][2*j+1][2], acc[mt][2*j+1][3]);
            a2[mt][j][0] = *reinterpret_cast<uint32_t*>(&h0);
            a2[mt][j][1] = *reinterpret_cast<uint32_t*>(&h1);
            a2[mt][j][2] = *reinterpret_cast<uint32_t*>(&h2);
            a2[mt][j][3] = *reinterpret_cast<uint32_t*>(&h3);
        }

    CP_WAIT(0);
    __syncthreads();

    // ---- stage 2: out = relu(z1 @ M^T + bias), N in 4 chunks of 64 ----
    const float* bias = (*step_p == 2) ? bias_b : bias_aux;
    const int g  = lane >> 2;
    const int tq = lane & 3;
    const uint32_t brow2 = (uint32_t)(((lane >> 4) << 3) + m7) * 256;

    #pragma unroll
    for (int c = 0; c < 4; ++c) {
        float acc2[2][8][4];
        #pragma unroll
        for (int mt = 0; mt < 2; ++mt)
            #pragma unroll
            for (int nt = 0; nt < 8; ++nt)
                #pragma unroll
                for (int q = 0; q < 4; ++q) acc2[mt][nt][q] = 0.f;

        const uint32_t Bb = sb + c * (64 * 256);
        #pragma unroll
        for (int ks = 0; ks < 8; ++ks) {
            const uint32_t cB = (uint32_t)(((ks * 2 + khB) ^ m7) << 4);
            uint32_t bf[4][4];
            #pragma unroll
            for (int np = 0; np < 4; ++np)
                LDSM_X4(bf[np][0], bf[np][1], bf[np][2], bf[np][3],
                        Bb + brow2 + np * (16 * 256) + cB);
            #pragma unroll
            for (int mt = 0; mt < 2; ++mt)
                #pragma unroll
                for (int nt = 0; nt < 8; ++nt)
                    MMA_F16(acc2[mt][nt],
                            a2[mt][ks][0], a2[mt][ks][1],
                            a2[mt][ks][2], a2[mt][ks][3],
                            bf[nt >> 1][(nt & 1) * 2],
                            bf[nt >> 1][(nt & 1) * 2 + 1]);
        }

        const int Nbase = c * 64;
        #pragma unroll
        for (int mt = 0; mt < 2; ++mt) {
            const int r0 = Mbase + mwarp * 32 + mt * 16 + g;
            #pragma unroll
            for (int half = 0; half < 2; ++half) {
                const int r = r0 + half * 8;
                const int bi = r / HW;
                const int rr = r - bi * HW;
                const float* bp = bias + (size_t)rr * FILTERS;
                float* op = out + (size_t)r * FILTERS;
                #pragma unroll
                for (int nt = 0; nt < 8; ++nt) {
                    const int col = Nbase + nt * 8 + tq * 2;
                    const float2 bv = *reinterpret_cast<const float2*>(bp + col);
                    float2 o;
                    o.x = fmaxf(acc2[mt][nt][half * 2 + 0] + bv.x, 0.f);
                    o.y = fmaxf(acc2[mt][nt][half * 2 + 1] + bv.y, 0.f);
                    *reinterpret_cast<float2*>(op + col) = o;
                }
            }
        }
    }
}

// ---------------------------------------------------------------------------
// Inputs: 0:x 1:k 2:l_t 3:s 4:aux_U 5:aux_Unp1 6:aux_Vt 7:aux_Vtnp1
//         8:b 9:aux_b 10:step
// ---------------------------------------------------------------------------
extern "C" void kernel_launch(void* const* d_in, const int* in_sizes, int n_in,
                              void* d_out, int out_size) {
    const float* x         = (const float*)d_in[0];
    const float* k_        = (const float*)d_in[1];
    const float* l_t       = (const float*)d_in[2];
    const float* s         = (const float*)d_in[3];
    const float* aux_U     = (const float*)d_in[4];
    const float* aux_Unp1  = (const float*)d_in[5];
    const float* aux_Vt    = (const float*)d_in[6];
    const float* aux_Vtnp1 = (const float*)d_in[7];
    const float* bias_b    = (const float*)d_in[8];
    const float* bias_aux  = (const float*)d_in[9];
    const int*   step_p    = (const int*)d_in[10];
    float* out = (float*)d_out;

    static bool cfg_done = false;
    if (!cfg_done) {
        cudaFuncSetAttribute(conv_fused,
                             cudaFuncAttributeMaxDynamicSharedMemorySize, SM_TOTAL);
        cfg_done = true;
    }

    prep_all<<<NFOLD + NCONVBLK, 256>>>(x, k_, l_t, s, aux_U, aux_Unp1,
                                        aux_Vt, aux_Vtnp1, step_p);
    conv_fused<<<PIX / CTA_M, NT, SM_TOTAL>>>(bias_b, bias_aux, step_p, out);
}

// round 17
// speedup vs baseline: 1.2114x; 1.1097x over previous
#include <cuda_runtime.h>
#include <cuda_fp16.h>
#include <cstdint>

// Problem constants
#define Bn 8
#define Hn 224
#define Wn 224
#define Cn 64
#define IN_DIM 576
#define RANKn 100
#define RPAD 112                      // rank padded to 7x16 (was 128)
#define NRT (RPAD / 8)                // 14 stage-1 n-tiles
#define NKF (RPAD / 16)               // 7 stage-2 k-fragments
#define FILTERS 256
#define HW 50176
#define PIX (Bn * HW)                 // 401408
#define XTOT (PIX * Cn)
#define NCONVBLK (XTOT / 16 / 256)    // 6272
#define NFOLD (RPAD + FILTERS)        // 368

// Fused tiling: CTA 128 pixels x 112 rank; 4 warps stacked in M (32 rows each)
#define CTA_M 128
#define BK 64
#define NT 128
#define KITERS (IN_DIM / BK)          // 9
#define STAGE_BYTES 32768             // A 16KB + B 16KB (B uses 14KB)
#define NSTAGE 3
#define SM_TOTAL (NSTAGE * STAGE_BYTES)   // 96KB -> 2 CTAs/SM

// Device-global scratch
__device__ __half g_Uh[RPAD * IN_DIM];      // U^T padded  [r][k]
__device__ __half g_M2h[FILTERS * RPAD];    // M^T padded  [n][r], stride 112
__device__ __half g_xh[XTOT];               // x fp16

// ---------------------------------------------------------------------------
__device__ __forceinline__ uint32_t smem_u32(const void* p) {
    uint32_t a;
    asm("{ .reg .u64 t; cvta.to.shared.u64 t, %1; cvt.u32.u64 %0, t; }"
        : "=r"(a) : "l"(p));
    return a;
}
#define CP_ASYNC_Z(d, s, sz) \
    asm volatile("cp.async.cg.shared.global [%0], [%1], 16, %2;" \
                 :: "r"(d), "l"(s), "r"(sz))
#define CP_ASYNC16(d, s) \
    asm volatile("cp.async.cg.shared.global [%0], [%1], 16;" :: "r"(d), "l"(s))
#define CP_COMMIT() asm volatile("cp.async.commit_group;" ::: "memory")
#define CP_WAIT(n)  asm volatile("cp.async.wait_group %0;" :: "n"(n) : "memory")

#define LDSM_X4(r0, r1, r2, r3, a) \
    asm volatile("ldmatrix.sync.aligned.m8n8.x4.shared.b16 {%0,%1,%2,%3}, [%4];" \
                 : "=r"(r0), "=r"(r1), "=r"(r2), "=r"(r3) : "r"(a))

#define MMA_F16(c, a0, a1, a2, a3, b0, b1)                                  \
    asm volatile("mma.sync.aligned.m16n8k16.row.col.f32.f16.f16.f32 "       \
                 "{%0,%1,%2,%3}, {%4,%5,%6,%7}, {%8,%9}, {%0,%1,%2,%3};"    \
                 : "+f"((c)[0]), "+f"((c)[1]), "+f"((c)[2]), "+f"((c)[3])   \
                 : "r"(a0), "r"(a1), "r"(a2), "r"(a3), "r"(b0), "r"(b1))

// ---------------------------------------------------------------------------
// Fused prep: [0,RPAD) U^T rows; [RPAD,NFOLD) M^T rows; rest: x -> fp16.
// ---------------------------------------------------------------------------
__global__ void __launch_bounds__(256, 8)
prep_all(const float* __restrict__ x,
         const float* __restrict__ k_,
         const float* __restrict__ l_t,
         const float* __restrict__ s,
         const float* __restrict__ aux_U,
         const float* __restrict__ aux_Unp1,
         const float* __restrict__ aux_Vt,
         const float* __restrict__ aux_Vtnp1,
         const int* __restrict__ step_p) {
    const int tid = threadIdx.x;
    if (blockIdx.x >= NFOLD) {
        size_t idx = ((size_t)(blockIdx.x - NFOLD) * 256 + tid) * 16;
        const float4* xp = reinterpret_cast<const float4*>(x + idx);
        #pragma unroll
        for (int h = 0; h < 2; ++h) {
            float4 v0 = xp[h * 2 + 0];
            float4 v1 = xp[h * 2 + 1];
            __half2 hh[4];
            hh[0] = __float22half2_rn(make_float2(v0.x, v0.y));
            hh[1] = __float22half2_rn(make_float2(v0.z, v0.w));
            hh[2] = __float22half2_rn(make_float2(v1.x, v1.y));
            hh[3] = __float22half2_rn(make_float2(v1.z, v1.w));
            *reinterpret_cast<uint4*>(g_xh + idx + h * 8) =
                *reinterpret_cast<uint4*>(hh);
        }
        return;
    }
    const int st = *step_p;
    if (blockIdx.x < RPAD) {
        const int r = blockIdx.x;
        const float* U = (st == 0) ? k_ : (st == 1) ? aux_U : aux_Unp1;
        for (int k = tid; k < IN_DIM; k += 256) {
            float v = (r < RANKn) ? U[(size_t)k * RANKn + r] : 0.f;
            g_Uh[(size_t)r * IN_DIM + k] = __float2half_rn(v);
        }
        return;
    }
    __shared__ float VtCol[RANKn];
    __shared__ float Ms[RANKn];
    const int n = blockIdx.x - RPAD;
    if (st == 2) {
        if (tid < RANKn) VtCol[tid] = aux_Vtnp1[(size_t)tid * FILTERS + n];
        __syncthreads();
        if (tid < RANKn) {
            const float* sr = s + (size_t)tid * RANKn;
            float acc = 0.f;
            for (int q = 0; q < RANKn; ++q) acc += sr[q] * VtCol[q];
            Ms[tid] = acc;
        }
    } else {
        const float* V = (st == 0) ? aux_Vt : l_t;
        if (tid < RANKn) Ms[tid] = V[(size_t)tid * FILTERS + n];
    }
    __syncthreads();
    if (tid < RPAD)
        g_M2h[(size_t)n * RPAD + tid] =
            (tid < RANKn) ? __float2half_rn(Ms[tid]) : __float2half_rn(0.f);
}

// ---------------------------------------------------------------------------
// Fused main: stage 1 (patches @ U^T, rank=112) -> acc regs -> fp16 pack ->
// stage 2 (z1 @ M^T, K=112) from registers. z1 never touches memory.
// ---------------------------------------------------------------------------
__global__ void __launch_bounds__(NT, 2)
conv_fused(const float* __restrict__ bias_b,
           const float* __restrict__ bias_aux,
           const int* __restrict__ step_p,
           float* __restrict__ out) {
    extern __shared__ __align__(128) char smem[];
    const int tid  = threadIdx.x;
    const int lane = tid & 31;
    const int mwarp = tid >> 5;           // 0..3, M-stacked warps
    const int Mbase = blockIdx.x * CTA_M;
    const uint32_t sb = smem_u32(smem);

    // Loader geometry (packed coords)
    const int jA  = tid & 7;
    const int rA  = tid >> 3;
    uint32_t pc[8];
    #pragma unroll
    for (int l = 0; l < 8; ++l) {
        int p = Mbase + l * 16 + rA;
        int bi = p / HW;
        int rem = p - bi * HW;
        int h = rem / Wn;
        int w = rem - h * Wn;
        pc[l] = ((uint32_t)bi << 16) | ((uint32_t)h << 8) | (uint32_t)w;
    }

    float acc[2][NRT][4];                 // 32 M x 112 N(rank) per warp
    #pragma unroll
    for (int mt = 0; mt < 2; ++mt)
        #pragma unroll
        for (int nt = 0; nt < NRT; ++nt)
            #pragma unroll
            for (int q = 0; q < 4; ++q) acc[mt][nt][q] = 0.f;

    auto load_stage = [&](int ko) {
        const int stage = ko % NSTAGE;
        const int dh = ko / 3 - 1;
        const int dw = ko % 3 - 1;
        const uint32_t dA = sb + stage * STAGE_BYTES;
        #pragma unroll
        for (int l = 0; l < 8; ++l) {
            const int row = l * 16 + rA;
            const int hh = (int)((pc[l] >> 8) & 255u) + dh;
            const int ww = (int)(pc[l] & 255u) + dw;
            const int bi = (int)(pc[l] >> 16);
            const bool ok = ((unsigned)hh < (unsigned)Hn) &&
                            ((unsigned)ww < (unsigned)Wn);
            const __half* sp = ok
                ? g_xh + (((size_t)bi * Hn + hh) * Wn + ww) * Cn + jA * 8
                : g_xh;
            CP_ASYNC_Z(dA + row * 128 + ((jA ^ (row & 7)) << 4), sp, ok ? 16u : 0u);
        }
        const int k0 = ko * BK;
        const uint32_t dB = dA + 16384;
        #pragma unroll
        for (int l = 0; l < 7; ++l) {     // 112 rank rows
            const int n = l * 16 + rA;
            const __half* bs = g_Uh + (size_t)n * IN_DIM + k0 + jA * 8;
            CP_ASYNC16(dB + n * 128 + ((jA ^ (n & 7)) << 4), bs);
        }
    };

    // Fragment addressing
    const int m7  = lane & 7;
    const int khA = lane >> 4;
    const int khB = (lane >> 3) & 1;
    const uint32_t arow = (uint32_t)(mwarp * 32 + (lane & 15)) * 128;
    const uint32_t brow = (uint32_t)(((lane >> 4) << 3) + m7) * 128;
    uint32_t coffA[4], coffB[4];
    #pragma unroll
    for (int ks = 0; ks < 4; ++ks) {
        coffA[ks] = (uint32_t)(((ks * 2 + khA) ^ m7) << 4);
        coffB[ks] = (uint32_t)(((ks * 2 + khB) ^ m7) << 4);
    }

    load_stage(0); CP_COMMIT();
    load_stage(1); CP_COMMIT();

    for (int ko = 0; ko < KITERS; ++ko) {
        if (ko < KITERS - 1) CP_WAIT(1);
        else                 CP_WAIT(0);
        __syncthreads();
        if (ko + 2 < KITERS) { load_stage(ko + 2); CP_COMMIT(); }

        const uint32_t As = sb + (ko % NSTAGE) * STAGE_BYTES;
        const uint32_t Bs = As + 16384;
        #pragma unroll
        for (int ks = 0; ks < 4; ++ks) {
            uint32_t bf[7][4];
            #pragma unroll
            for (int np = 0; np < 7; ++np)
                LDSM_X4(bf[np][0], bf[np][1], bf[np][2], bf[np][3],
                        Bs + brow + np * (16 * 128) + coffB[ks]);
            uint32_t a[2][4];
            #pragma unroll
            for (int mt = 0; mt < 2; ++mt)
                LDSM_X4(a[mt][0], a[mt][1], a[mt][2], a[mt][3],
                        As + arow + mt * (16 * 128) + coffA[ks]);
            #pragma unroll
            for (int mt = 0; mt < 2; ++mt)
                #pragma unroll
                for (int nt = 0; nt < NRT; ++nt)
                    MMA_F16(acc[mt][nt], a[mt][0], a[mt][1], a[mt][2], a[mt][3],
                            bf[nt >> 1][(nt & 1) * 2],
                            bf[nt >> 1][(nt & 1) * 2 + 1]);
        }
    }

    // ---- register handoff ------------------------------------------------
    __syncthreads();   // all stage buffers dead

    // Prefetch full M2: 256 rows x 14 chunks of 16B, smem stride 256B (64KB)
    #pragma unroll
    for (int l = 0; l < 32; ++l) {
        int idx = l * NT + tid;
        int row = idx >> 4, j = idx & 15;
        if (j < 14) {
            const __half* bsrc = g_M2h + (size_t)row * RPAD + j * 8;
            CP_ASYNC16(sb + row * 256 + ((j ^ (row & 7)) << 4), bsrc);
        }
    }
    CP_COMMIT();

    // Pack acc -> stage-2 A fragments (m16k16): fragment j <- n-tiles (2j,2j+1)
    uint32_t a2[2][NKF][4];
    #pragma unroll
    for (int mt = 0; mt < 2; ++mt)
        #pragma unroll
        for (int j = 0; j < NKF; ++j) {
            __half2 h0 = __floats2half2_rn(acc[mt][2*j][0],   acc[mt][2*j][1]);
            __half2 h1 = __floats2half2_rn(acc[mt][2*j][2],   acc[mt][2*j][3]);
            __half2 h2 = __floats2half2_rn(acc[mt][2*j+1][0], acc[mt][2*j+1][1]);
            __half2 h3 = __floats2half2_rn(acc[mt][2*j+1][2], acc[mt][2*j+1][3]);
            a2[mt][j][0] = *reinterpret_cast<uint32_t*>(&h0);
            a2[mt][j][1] = *reinterpret_cast<uint32_t*>(&h1);
            a2[mt][j][2] = *reinterpret_cast<uint32_t*>(&h2);
            a2[mt][j][3] = *reinterpret_cast<uint32_t*>(&h3);
        }

    CP_WAIT(0);
    __syncthreads();

    // ---- stage 2: out = relu(z1 @ M^T + bias), N in 4 chunks of 64 ----
    const float* bias = (*step_p == 2) ? bias_b : bias_aux;
    const int g  = lane >> 2;
    const int tq = lane & 3;
    const uint32_t brow2 = (uint32_t)(((lane >> 4) << 3) + m7) * 256;

    #pragma unroll
    for (int c = 0; c < 4; ++c) {
        float acc2[2][8][4];
        #pragma unroll
        for (int mt = 0; mt < 2; ++mt)
            #pragma unroll
            for (int nt = 0; nt < 8; ++nt)
                #pragma unroll
                for (int q = 0; q < 4; ++q) acc2[mt][nt][q] = 0.f;

        const uint32_t Bb = sb + c * (64 * 256);
        #pragma unroll
        for (int ks = 0; ks < NKF; ++ks) {
            const uint32_t cB = (uint32_t)(((ks * 2 + khB) ^ m7) << 4);
            uint32_t bf[4][4];
            #pragma unroll
            for (int np = 0; np < 4; ++np)
                LDSM_X4(bf[np][0], bf[np][1], bf[np][2], bf[np][3],
                        Bb + brow2 + np * (16 * 256) + cB);
            #pragma unroll
            for (int mt = 0; mt < 2; ++mt)
                #pragma unroll
                for (int nt = 0; nt < 8; ++nt)
                    MMA_F16(acc2[mt][nt],
                            a2[mt][ks][0], a2[mt][ks][1],
                            a2[mt][ks][2], a2[mt][ks][3],
                            bf[nt >> 1][(nt & 1) * 2],
                            bf[nt >> 1][(nt & 1) * 2 + 1]);
        }

        const int Nbase = c * 64;
        #pragma unroll
        for (int mt = 0; mt < 2; ++mt) {
            const int r0 = Mbase + mwarp * 32 + mt * 16 + g;
            #pragma unroll
            for (int half = 0; half < 2; ++half) {
                const int r = r0 + half * 8;
                const int bi = r / HW;
                const int rr = r - bi * HW;
                const float* bp = bias + (size_t)rr * FILTERS;
                float* op = out + (size_t)r * FILTERS;
                #pragma unroll
                for (int nt = 0; nt < 8; ++nt) {
                    const int col = Nbase + nt * 8 + tq * 2;
                    const float2 bv = *reinterpret_cast<const float2*>(bp + col);
                    float2 o;
                    o.x = fmaxf(acc2[mt][nt][half * 2 + 0] + bv.x, 0.f);
                    o.y = fmaxf(acc2[mt][nt][half * 2 + 1] + bv.y, 0.f);
                    *reinterpret_cast<float2*>(op + col) = o;
                }
            }
        }
    }
}

// ---------------------------------------------------------------------------
// Inputs: 0:x 1:k 2:l_t 3:s 4:aux_U 5:aux_Unp1 6:aux_Vt 7:aux_Vtnp1
//         8:b 9:aux_b 10:step
// ---------------------------------------------------------------------------
extern "C" void kernel_launch(void* const* d_in, const int* in_sizes, int n_in,
                              void* d_out, int out_size) {
    const float* x         = (const float*)d_in[0];
    const float* k_        = (const float*)d_in[1];
    const float* l_t       = (const float*)d_in[2];
    const float* s         = (const float*)d_in[3];
    const float* aux_U     = (const float*)d_in[4];
    const float* aux_Unp1  = (const float*)d_in[5];
    const float* aux_Vt    = (const float*)d_in[6];
    const float* aux_Vtnp1 = (const float*)d_in[7];
    const float* bias_b    = (const float*)d_in[8];
    const float* bias_aux  = (const float*)d_in[9];
    const int*   step_p    = (const int*)d_in[10];
    float* out = (float*)d_out;

    static bool cfg_done = false;
    if (!cfg_done) {
        cudaFuncSetAttribute(conv_fused,
                             cudaFuncAttributeMaxDynamicSharedMemorySize, SM_TOTAL);
        cfg_done = true;
    }

    prep_all<<<NFOLD + NCONVBLK, 256>>>(x, k_, l_t, s, aux_U, aux_Unp1,
                                        aux_Vt, aux_Vtnp1, step_p);
    conv_fused<<<PIX / CTA_M, NT, SM_TOTAL>>>(bias_b, bias_aux, step_p, out);
}